// round 2
// baseline (speedup 1.0000x reference)
#include <cuda_runtime.h>

// ---------------- problem constants ----------------
constexpr int NUc = 100000;
constexpr int NIc = 50000;
constexpr int Dc  = 64;
constexpr int EBc = 500000;
constexpr int ECc = 1000000;
constexpr int EPc = 2000000;
constexpr long long ETOTD = (long long)(EBc + ECc + EPc) * Dc; // 224M floats

constexpr int NUD = NUc * Dc;  // 6.4M
constexpr int NID = NIc * Dc;  // 3.2M

constexpr float A_SC = 0.0045f;
constexpr float B_SC = 0.0045f;

// zbuf layout: aggU[3][NUD] | aggD[3][NID] | se[3][NUD] | de[3][NID]
constexpr size_t ZB_AGGU = 0;
constexpr size_t ZB_AGGD = (size_t)3 * NUD;
constexpr size_t ZB_SE   = ZB_AGGD + (size_t)3 * NID;
constexpr size_t ZB_DE   = ZB_SE + (size_t)3 * NUD;
constexpr size_t ZTOT    = ZB_DE + (size_t)3 * NID;   // 57.6M floats

// ---------------- device scratch (no allocation allowed) ----------------
__device__ float g_zbuf[ZTOT];
__device__ float g_seW[(size_t)3 * NUD];
__device__ float g_deW[(size_t)3 * NID];
__device__ float g_src[NUD];
__device__ float g_dst[NID];
__device__ float g_srcAll[NUD];
__device__ float g_dstAll[NID];
__device__ float g_enew[ETOTD];                 // updated edge feats (layer 0 -> 1)
__device__ int   g_deg[3 * NUc + 3 * NIc];
__device__ float g_isqU[3 * NUc];
__device__ float g_isqV[3 * NIc];
__device__ float g_dU[3 * NUc];
__device__ float g_dV[3 * NIc];

__device__ __forceinline__ size_t eofs(int t) {
    return t == 0 ? 0 : (t == 1 ? (size_t)EBc * Dc : (size_t)(EBc + ECc) * Dc);
}

__device__ __forceinline__ float lrelu(float x) { return x >= 0.0f ? x : 0.01f * x; }

__device__ __forceinline__ void red4(float4* a, float x, float y, float z, float w) {
    asm volatile("red.global.add.v4.f32 [%0], {%1, %2, %3, %4};"
                 :: "l"(a), "f"(x), "f"(y), "f"(z), "f"(w) : "memory");
}

// ---------------- kernels ----------------

__global__ void zeroF_k() {
    long long i = (long long)blockIdx.x * blockDim.x + threadIdx.x;
    if (i < (long long)(ZTOT / 4)) ((float4*)g_zbuf)[i] = make_float4(0.f, 0.f, 0.f, 0.f);
}

__global__ void zeroDeg_k() {
    int i = blockIdx.x * blockDim.x + threadIdx.x;
    if (i < 3 * (NUc + NIc)) g_deg[i] = 0;
}

__global__ void degCount_k(int t, const int* __restrict__ U, const int* __restrict__ V, int E) {
    int e = blockIdx.x * blockDim.x + threadIdx.x;
    if (e >= E) return;
    atomicAdd(&g_deg[t * NUc + U[e]], 1);
    atomicAdd(&g_deg[3 * NUc + t * NIc + V[e]], 1);
}

__global__ void degConv_k() {
    int i = blockIdx.x * blockDim.x + threadIdx.x;
    if (i < 3 * NUc) {
        float f = (float)max(g_deg[i], 1);
        g_dU[i] = f;
        g_isqU[i] = rsqrtf(f);
    } else if (i < 3 * (NUc + NIc)) {
        int j = i - 3 * NUc;
        float f = (float)max(g_deg[3 * NUc + j], 1);
        g_dV[j] = f;
        g_isqV[j] = rsqrtf(f);
    }
}

__global__ void scaleInit_k(const float* __restrict__ emb, int items) {
    int i = blockIdx.x * blockDim.x + threadIdx.x;
    int n = items ? NID : NUD;
    if (i >= n) return;
    float v = emb[i] * A_SC;
    if (items) { g_dst[i] = v; g_dstAll[i] = v; }
    else       { g_src[i] = v; g_srcAll[i] = v; }
}

// Fused edge pass: forward gconv scatter, reverse gconv scatter, se/de segment sums.
// 16 threads per edge, float4 per thread.
__global__ void edgeA_k(const float* __restrict__ ew_ext, int use_ext, int t,
                        const int* __restrict__ U, const int* __restrict__ V,
                        int E, float esc) {
    long long g = (long long)blockIdx.x * blockDim.x + threadIdx.x;
    if (g >= (long long)E * 16) return;
    int e = (int)(g >> 4);
    int q = (int)(g & 15);
    int u = U[e], v = V[e];
    float su = g_isqU[t * NUc + u];
    float sv = g_isqV[t * NIc + v];

    const float4* ew4 = (const float4*)(use_ext ? ew_ext : (const float*)(g_enew + eofs(t)));
    float4 w = __ldg(ew4 + (long long)e * 16 + q);
    w.x *= esc; w.y *= esc; w.z *= esc; w.w *= esc;

    float4 s = ((const float4*)g_src)[u * 16 + q];
    float4 d = ((const float4*)g_dst)[v * 16 + q];

    float4* aggU = (float4*)(g_zbuf + ZB_AGGU + (size_t)t * NUD);
    float4* aggD = (float4*)(g_zbuf + ZB_AGGD + (size_t)t * NID);
    float4* se   = (float4*)(g_zbuf + ZB_SE   + (size_t)t * NUD);
    float4* de   = (float4*)(g_zbuf + ZB_DE   + (size_t)t * NID);

    red4(&aggD[v * 16 + q], s.x * su * w.x, s.y * su * w.y, s.z * su * w.z, s.w * su * w.w);
    red4(&aggU[u * 16 + q], d.x * sv * w.x, d.y * sv * w.y, d.z * sv * w.z, d.w * sv * w.w);
    red4(&se[u * 16 + q], w.x, w.y, w.z, w.w);
    red4(&de[v * 16 + q], w.x, w.y, w.z, w.w);
}

// dst_new = sum_t w_t * leaky((aggD_t @ Wn) * isqV_t)  (and same for src side)
__global__ void nodeCombine_k(const float* __restrict__ W, int items) {
    __shared__ float Ws[64 * 64];
    __shared__ float R[4][3][64];
    int tx = threadIdx.x, ty = threadIdx.y;
    int lin = ty * 64 + tx;
#pragma unroll
    for (int i = 0; i < 16; i++) Ws[lin + 256 * i] = W[lin + 256 * i];

    int N = items ? NIc : NUc;
    int nd = items ? NID : NUD;
    int n = blockIdx.x * 4 + ty;
    const float* agg = items ? (g_zbuf + ZB_AGGD) : (g_zbuf + ZB_AGGU);
    if (n < N) {
        R[ty][0][tx] = agg[(size_t)0 * nd + n * 64 + tx];
        R[ty][1][tx] = agg[(size_t)1 * nd + n * 64 + tx];
        R[ty][2][tx] = agg[(size_t)2 * nd + n * 64 + tx];
    }
    __syncthreads();
    if (n >= N) return;

    float s0 = 0.f, s1 = 0.f, s2 = 0.f;
#pragma unroll
    for (int k = 0; k < 64; k++) {
        float wk = Ws[k * 64 + tx];
        s0 = fmaf(R[ty][0][k], wk, s0);
        s1 = fmaf(R[ty][1][k], wk, s1);
        s2 = fmaf(R[ty][2][k], wk, s2);
    }
    const float* isq = items ? g_isqV : g_isqU;
    int NN = items ? NIc : NUc;
    float o = lrelu(s0 * isq[0 * NN + n]) + 0.5f * lrelu(s1 * isq[1 * NN + n])
            + 0.25f * lrelu(s2 * isq[2 * NN + n]);
    float* cur = items ? g_dst : g_src;
    float* acc = items ? g_dstAll : g_srcAll;
    cur[n * 64 + tx] = o;
    acc[n * 64 + tx] += o;
}

// seW_t = se_t @ We  (node-sized GEMM; the big per-edge GEMM hoisted to nodes)
__global__ void seGemm_k(const float* __restrict__ W, int t, int items) {
    __shared__ float Ws[64 * 64];
    __shared__ float R[4][64];
    int tx = threadIdx.x, ty = threadIdx.y;
    int lin = ty * 64 + tx;
#pragma unroll
    for (int i = 0; i < 16; i++) Ws[lin + 256 * i] = W[lin + 256 * i];

    int N = items ? NIc : NUc;
    const float* in  = items ? (g_zbuf + ZB_DE + (size_t)t * NID)
                             : (g_zbuf + ZB_SE + (size_t)t * NUD);
    float* out = items ? (g_deW + (size_t)t * NID) : (g_seW + (size_t)t * NUD);
    int n = blockIdx.x * 4 + ty;
    if (n < N) R[ty][tx] = in[n * 64 + tx];
    __syncthreads();
    if (n >= N) return;

    float s = 0.f;
#pragma unroll
    for (int k = 0; k < 64; k++) s = fmaf(R[ty][k], Ws[k * 64 + tx], s);
    out[n * 64 + tx] = s;
}

// edge update: e_new = leaky((seW[u] + deW[v]) / (dU[u] + dV[v]))
__global__ void edgeC_k(int t, const int* __restrict__ U, const int* __restrict__ V, int E) {
    long long g = (long long)blockIdx.x * blockDim.x + threadIdx.x;
    if (g >= (long long)E * 16) return;
    int e = (int)(g >> 4);
    int q = (int)(g & 15);
    int u = U[e], v = V[e];
    float r = 1.0f / (g_dU[t * NUc + u] + g_dV[t * NIc + v]);
    const float4* sw = (const float4*)(g_seW + (size_t)t * NUD);
    const float4* dw = (const float4*)(g_deW + (size_t)t * NID);
    float4 s = __ldg(sw + u * 16 + q);
    float4 d = __ldg(dw + v * 16 + q);
    float4 o;
    o.x = lrelu((s.x + d.x) * r);
    o.y = lrelu((s.y + d.y) * r);
    o.z = lrelu((s.z + d.z) * r);
    o.w = lrelu((s.w + d.w) * r);
    ((float4*)(g_enew + eofs(t)))[(long long)e * 16 + q] = o;
}

__global__ void writeOut_k(float* __restrict__ out) {
    int i = blockIdx.x * blockDim.x + threadIdx.x;
    if (i < NUD) out[i] = g_srcAll[i] / 3.0f;
    else if (i < NUD + NID) out[i] = g_dstAll[i - NUD] / 3.0f;
}

// ---------------- launch ----------------
extern "C" void kernel_launch(void* const* d_in, const int* in_sizes, int n_in,
                              void* d_out, int out_size) {
    const float* user  = (const float*)d_in[0];
    const float* item  = (const float*)d_in[1];
    const float* ebuy  = (const float*)d_in[2];
    const float* ecart = (const float*)d_in[3];
    const float* epv   = (const float*)d_in[4];
    const float* nodeW = (const float*)d_in[5];
    const float* edgeW = (const float*)d_in[6];
    const int* bu = (const int*)d_in[7];
    const int* bv = (const int*)d_in[8];
    const int* cu = (const int*)d_in[9];
    const int* cv = (const int*)d_in[10];
    const int* pu = (const int*)d_in[11];
    const int* pvv = (const int*)d_in[12];
    float* out = (float*)d_out;

    const int TB = 256;
    auto nb = [](long long n, int tb) { return (unsigned)((n + tb - 1) / tb); };

    // degrees (recomputed every call; deterministic)
    zeroDeg_k<<<nb(3 * (NUc + NIc), TB), TB>>>();
    degCount_k<<<nb(EBc, TB), TB>>>(0, bu, bv, EBc);
    degCount_k<<<nb(ECc, TB), TB>>>(1, cu, cv, ECc);
    degCount_k<<<nb(EPc, TB), TB>>>(2, pu, pvv, EPc);
    degConv_k<<<nb(3 * (NUc + NIc), TB), TB>>>();

    scaleInit_k<<<nb(NUD, TB), TB>>>(user, 0);
    scaleInit_k<<<nb(NID, TB), TB>>>(item, 1);

    dim3 bt(64, 4);
    for (int layer = 0; layer < 2; layer++) {
        zeroF_k<<<nb((long long)(ZTOT / 4), TB), TB>>>();
        const float* Wn = nodeW + layer * Dc * Dc;
        float esc = (layer == 0) ? B_SC : 1.0f;
        int ue = (layer == 0) ? 1 : 0;

        edgeA_k<<<nb((long long)EBc * 16, TB), TB>>>(ebuy, ue, 0, bu, bv, EBc, esc);
        edgeA_k<<<nb((long long)ECc * 16, TB), TB>>>(ecart, ue, 1, cu, cv, ECc, esc);
        edgeA_k<<<nb((long long)EPc * 16, TB), TB>>>(epv, ue, 2, pu, pvv, EPc, esc);

        nodeCombine_k<<<nb(NIc, 4), bt>>>(Wn, 1);
        nodeCombine_k<<<nb(NUc, 4), bt>>>(Wn, 0);

        if (layer == 0) {  // last layer's edge update is dead code
            const float* We = edgeW;  // edge_W[0]
            for (int t = 0; t < 3; t++) {
                seGemm_k<<<nb(NUc, 4), bt>>>(We, t, 0);
                seGemm_k<<<nb(NIc, 4), bt>>>(We, t, 1);
            }
            edgeC_k<<<nb((long long)EBc * 16, TB), TB>>>(0, bu, bv, EBc);
            edgeC_k<<<nb((long long)ECc * 16, TB), TB>>>(1, cu, cv, ECc);
            edgeC_k<<<nb((long long)EPc * 16, TB), TB>>>(2, pu, pvv, EPc);
        }
    }
    writeOut_k<<<nb(NUD + NID, TB), TB>>>(out);
}

// round 3
// speedup vs baseline: 1.3268x; 1.3268x over previous
#include <cuda_runtime.h>

// ---------------- problem constants ----------------
constexpr int NUc = 100000;
constexpr int NIc = 50000;
constexpr int Dc  = 64;
constexpr int EBc = 500000;
constexpr int ECc = 1000000;
constexpr int EPc = 2000000;

constexpr int NUD = NUc * Dc;  // 6.4M
constexpr int NID = NIc * Dc;  // 3.2M

constexpr float A_SC = 0.0045f;
constexpr float B_SC = 0.0045f;

// zbuf layout: aggU[3][NUD] | aggD[3][NID] | se[3][NUD] | de[3][NID]
constexpr size_t ZB_AGGU = 0;
constexpr size_t ZB_AGGD = (size_t)3 * NUD;
constexpr size_t ZB_SE   = ZB_AGGD + (size_t)3 * NID;
constexpr size_t ZB_DE   = ZB_SE + (size_t)3 * NUD;
constexpr size_t ZTOT    = ZB_DE + (size_t)3 * NID;   // 57.6M floats
constexpr size_t ZAGG    = ZB_SE;                      // aggU+aggD region size

// ---------------- device scratch (no allocation allowed) ----------------
__device__ float g_zbuf[ZTOT];
__device__ float g_seW[(size_t)3 * NUD];
__device__ float g_deW[(size_t)3 * NID];
__device__ float g_src[NUD];
__device__ float g_dst[NID];
__device__ float g_srcAll[NUD];
__device__ float g_dstAll[NID];
__device__ int   g_deg[3 * NUc + 3 * NIc];
__device__ float g_isqU[3 * NUc];
__device__ float g_isqV[3 * NIc];
__device__ float g_dU[3 * NUc];
__device__ float g_dV[3 * NIc];

__device__ __forceinline__ float lrelu(float x) { return x >= 0.0f ? x : 0.01f * x; }

__device__ __forceinline__ void red4(float4* a, float x, float y, float z, float w) {
    asm volatile("red.global.add.v4.f32 [%0], {%1, %2, %3, %4};"
                 :: "l"(a), "f"(x), "f"(y), "f"(z), "f"(w) : "memory");
}

// ---------------- kernels ----------------

__global__ void zeroRange_k(size_t off4, size_t n4) {
    size_t i = (size_t)blockIdx.x * blockDim.x + threadIdx.x;
    if (i < n4) ((float4*)g_zbuf)[off4 + i] = make_float4(0.f, 0.f, 0.f, 0.f);
}

__global__ void zeroDeg_k() {
    int i = blockIdx.x * blockDim.x + threadIdx.x;
    if (i < 3 * (NUc + NIc)) g_deg[i] = 0;
}

__global__ void degCount_k(int t, const int* __restrict__ U, const int* __restrict__ V, int E) {
    int e = blockIdx.x * blockDim.x + threadIdx.x;
    if (e >= E) return;
    atomicAdd(&g_deg[t * NUc + U[e]], 1);
    atomicAdd(&g_deg[3 * NUc + t * NIc + V[e]], 1);
}

__global__ void degConv_k() {
    int i = blockIdx.x * blockDim.x + threadIdx.x;
    if (i < 3 * NUc) {
        float f = (float)max(g_deg[i], 1);
        g_dU[i] = f;
        g_isqU[i] = rsqrtf(f);
    } else if (i < 3 * (NUc + NIc)) {
        int j = i - 3 * NUc;
        float f = (float)max(g_deg[3 * NUc + j], 1);
        g_dV[j] = f;
        g_isqV[j] = rsqrtf(f);
    }
}

__global__ void scaleInit_k(const float* __restrict__ emb, int items) {
    int i = blockIdx.x * blockDim.x + threadIdx.x;
    int n = items ? NID : NUD;
    if (i >= n) return;
    float v = emb[i] * A_SC;
    if (items) { g_dst[i] = v; g_dstAll[i] = v; }
    else       { g_src[i] = v; g_srcAll[i] = v; }
}

// Layer-0 fused edge pass: fwd gconv scatter, rev gconv scatter, se/de segment sums.
// 16 threads per edge, float4 per thread. Edge features streamed with .cs.
__global__ void __launch_bounds__(256) edgeA0_k(const float* __restrict__ ew_ext, int t,
                         const int* __restrict__ U, const int* __restrict__ V, int E) {
    long long g = (long long)blockIdx.x * blockDim.x + threadIdx.x;
    if (g >= (long long)E * 16) return;
    int e = (int)(g >> 4);
    int q = (int)(g & 15);
    int u = __ldg(U + e), v = __ldg(V + e);
    float su = g_isqU[t * NUc + u];
    float sv = g_isqV[t * NIc + v];

    float4 w = __ldcs((const float4*)ew_ext + (long long)e * 16 + q);  // streaming
    w.x *= B_SC; w.y *= B_SC; w.z *= B_SC; w.w *= B_SC;

    float4 s = __ldg((const float4*)g_src + u * 16 + q);
    float4 d = __ldg((const float4*)g_dst + v * 16 + q);

    float4* aggU = (float4*)(g_zbuf + ZB_AGGU + (size_t)t * NUD);
    float4* aggD = (float4*)(g_zbuf + ZB_AGGD + (size_t)t * NID);
    float4* se   = (float4*)(g_zbuf + ZB_SE   + (size_t)t * NUD);
    float4* de   = (float4*)(g_zbuf + ZB_DE   + (size_t)t * NID);

    red4(&aggD[v * 16 + q], s.x * su * w.x, s.y * su * w.y, s.z * su * w.z, s.w * su * w.w);
    red4(&aggU[u * 16 + q], d.x * sv * w.x, d.y * sv * w.y, d.z * sv * w.z, d.w * sv * w.w);
    red4(&se[u * 16 + q], w.x, w.y, w.z, w.w);
    red4(&de[v * 16 + q], w.x, w.y, w.z, w.w);
}

// Layer-1 fused edge pass: edge weight computed INLINE from node-hoisted edge
// update (w = lrelu((seW[u]+deW[v]) / (dU[u]+dV[v]))); no se/de scatter
// (dead after last layer), no materialized edge array (saves 1.8GB DRAM).
__global__ void __launch_bounds__(256) edgeB1_k(int t, const int* __restrict__ U,
                         const int* __restrict__ V, int E) {
    long long g = (long long)blockIdx.x * blockDim.x + threadIdx.x;
    if (g >= (long long)E * 16) return;
    int e = (int)(g >> 4);
    int q = (int)(g & 15);
    int u = __ldg(U + e), v = __ldg(V + e);
    float su = g_isqU[t * NUc + u];
    float sv = g_isqV[t * NIc + v];
    float r = 1.0f / (g_dU[t * NUc + u] + g_dV[t * NIc + v]);

    float4 sw = __ldg((const float4*)(g_seW + (size_t)t * NUD) + u * 16 + q);
    float4 dw = __ldg((const float4*)(g_deW + (size_t)t * NID) + v * 16 + q);
    float4 w;
    w.x = lrelu((sw.x + dw.x) * r);
    w.y = lrelu((sw.y + dw.y) * r);
    w.z = lrelu((sw.z + dw.z) * r);
    w.w = lrelu((sw.w + dw.w) * r);

    float4 s = __ldg((const float4*)g_src + u * 16 + q);
    float4 d = __ldg((const float4*)g_dst + v * 16 + q);

    float4* aggU = (float4*)(g_zbuf + ZB_AGGU + (size_t)t * NUD);
    float4* aggD = (float4*)(g_zbuf + ZB_AGGD + (size_t)t * NID);

    red4(&aggD[v * 16 + q], s.x * su * w.x, s.y * su * w.y, s.z * su * w.z, s.w * su * w.w);
    red4(&aggU[u * 16 + q], d.x * sv * w.x, d.y * sv * w.y, d.z * sv * w.z, d.w * sv * w.w);
}

// dst_new = sum_t wt_t * leaky((agg_t @ Wn) * isq_t); also accumulate into *_All
__global__ void nodeCombine_k(const float* __restrict__ W, int items) {
    __shared__ float Ws[64 * 64];
    __shared__ float R[4][3][64];
    int tx = threadIdx.x, ty = threadIdx.y;
    int lin = ty * 64 + tx;
#pragma unroll
    for (int i = 0; i < 16; i++) Ws[lin + 256 * i] = W[lin + 256 * i];

    int N = items ? NIc : NUc;
    int nd = items ? NID : NUD;
    int n = blockIdx.x * 4 + ty;
    const float* agg = items ? (g_zbuf + ZB_AGGD) : (g_zbuf + ZB_AGGU);
    if (n < N) {
        R[ty][0][tx] = agg[(size_t)0 * nd + n * 64 + tx];
        R[ty][1][tx] = agg[(size_t)1 * nd + n * 64 + tx];
        R[ty][2][tx] = agg[(size_t)2 * nd + n * 64 + tx];
    }
    __syncthreads();
    if (n >= N) return;

    float s0 = 0.f, s1 = 0.f, s2 = 0.f;
#pragma unroll
    for (int k = 0; k < 64; k++) {
        float wk = Ws[k * 64 + tx];
        s0 = fmaf(R[ty][0][k], wk, s0);
        s1 = fmaf(R[ty][1][k], wk, s1);
        s2 = fmaf(R[ty][2][k], wk, s2);
    }
    const float* isq = items ? g_isqV : g_isqU;
    int NN = items ? NIc : NUc;
    float o = lrelu(s0 * isq[0 * NN + n]) + 0.5f * lrelu(s1 * isq[1 * NN + n])
            + 0.25f * lrelu(s2 * isq[2 * NN + n]);
    float* cur = items ? g_dst : g_src;
    float* acc = items ? g_dstAll : g_srcAll;
    cur[n * 64 + tx] = o;
    acc[n * 64 + tx] += o;
}

// seW_t = se_t @ We / deW_t = de_t @ We  (per-edge GEMM hoisted to nodes)
__global__ void seGemm_k(const float* __restrict__ W, int t, int items) {
    __shared__ float Ws[64 * 64];
    __shared__ float R[4][64];
    int tx = threadIdx.x, ty = threadIdx.y;
    int lin = ty * 64 + tx;
#pragma unroll
    for (int i = 0; i < 16; i++) Ws[lin + 256 * i] = W[lin + 256 * i];

    int N = items ? NIc : NUc;
    const float* in  = items ? (g_zbuf + ZB_DE + (size_t)t * NID)
                             : (g_zbuf + ZB_SE + (size_t)t * NUD);
    float* out = items ? (g_deW + (size_t)t * NID) : (g_seW + (size_t)t * NUD);
    int n = blockIdx.x * 4 + ty;
    if (n < N) R[ty][tx] = in[n * 64 + tx];
    __syncthreads();
    if (n >= N) return;

    float s = 0.f;
#pragma unroll
    for (int k = 0; k < 64; k++) s = fmaf(R[ty][k], Ws[k * 64 + tx], s);
    out[n * 64 + tx] = s;
}

__global__ void writeOut_k(float* __restrict__ out) {
    int i = blockIdx.x * blockDim.x + threadIdx.x;
    if (i < NUD) out[i] = g_srcAll[i] / 3.0f;
    else if (i < NUD + NID) out[i] = g_dstAll[i - NUD] / 3.0f;
}

// ---------------- launch ----------------
extern "C" void kernel_launch(void* const* d_in, const int* in_sizes, int n_in,
                              void* d_out, int out_size) {
    const float* user  = (const float*)d_in[0];
    const float* item  = (const float*)d_in[1];
    const float* ebuy  = (const float*)d_in[2];
    const float* ecart = (const float*)d_in[3];
    const float* epv   = (const float*)d_in[4];
    const float* nodeW = (const float*)d_in[5];
    const float* edgeW = (const float*)d_in[6];
    const int* bu = (const int*)d_in[7];
    const int* bv = (const int*)d_in[8];
    const int* cu = (const int*)d_in[9];
    const int* cv = (const int*)d_in[10];
    const int* pu = (const int*)d_in[11];
    const int* pvv = (const int*)d_in[12];
    float* out = (float*)d_out;

    const int TB = 256;
    auto nb = [](long long n, int tb) { return (unsigned)((n + tb - 1) / tb); };

    // degrees (recomputed every call; deterministic)
    zeroDeg_k<<<nb(3 * (NUc + NIc), TB), TB>>>();
    degCount_k<<<nb(EBc, TB), TB>>>(0, bu, bv, EBc);
    degCount_k<<<nb(ECc, TB), TB>>>(1, cu, cv, ECc);
    degCount_k<<<nb(EPc, TB), TB>>>(2, pu, pvv, EPc);
    degConv_k<<<nb(3 * (NUc + NIc), TB), TB>>>();

    scaleInit_k<<<nb(NUD, TB), TB>>>(user, 0);
    scaleInit_k<<<nb(NID, TB), TB>>>(item, 1);

    dim3 bt(64, 4);

    // -------- layer 0 --------
    zeroRange_k<<<nb((long long)(ZTOT / 4), TB), TB>>>(0, ZTOT / 4);

    edgeA0_k<<<nb((long long)EBc * 16, TB), TB>>>(ebuy, 0, bu, bv, EBc);
    edgeA0_k<<<nb((long long)ECc * 16, TB), TB>>>(ecart, 1, cu, cv, ECc);
    edgeA0_k<<<nb((long long)EPc * 16, TB), TB>>>(epv, 2, pu, pvv, EPc);

    nodeCombine_k<<<nb(NIc, 4), bt>>>(nodeW, 1);
    nodeCombine_k<<<nb(NUc, 4), bt>>>(nodeW, 0);

    for (int t = 0; t < 3; t++) {
        seGemm_k<<<nb(NUc, 4), bt>>>(edgeW, t, 0);   // edge_W[0]
        seGemm_k<<<nb(NIc, 4), bt>>>(edgeW, t, 1);
    }

    // -------- layer 1 (edge update fused inline; se/de dead) --------
    zeroRange_k<<<nb((long long)(ZAGG / 4), TB), TB>>>(0, ZAGG / 4);

    edgeB1_k<<<nb((long long)EBc * 16, TB), TB>>>(0, bu, bv, EBc);
    edgeB1_k<<<nb((long long)ECc * 16, TB), TB>>>(1, cu, cv, ECc);
    edgeB1_k<<<nb((long long)EPc * 16, TB), TB>>>(2, pu, pvv, EPc);

    nodeCombine_k<<<nb(NIc, 4), bt>>>(nodeW + Dc * Dc, 1);
    nodeCombine_k<<<nb(NUc, 4), bt>>>(nodeW + Dc * Dc, 0);

    writeOut_k<<<nb(NUD + NID, TB), TB>>>(out);
}

// round 4
// speedup vs baseline: 1.5214x; 1.1466x over previous
#include <cuda_runtime.h>

// ---------------- problem constants ----------------
constexpr int NUc = 100000;
constexpr int NIc = 50000;
constexpr int Dc  = 64;
constexpr int EBc = 500000;
constexpr int ECc = 1000000;
constexpr int EPc = 2000000;
constexpr int ETOT_E = EBc + ECc + EPc;   // 3.5M

constexpr int NUD = NUc * Dc;  // 6.4M
constexpr int NID = NIc * Dc;  // 3.2M

constexpr float A_SC = 0.0045f;
constexpr float B_SC = 0.0045f;

// zbuf layout: aggU[3][NUD] | aggD[3][NID] | se[3][NUD] | de[3][NID]
constexpr size_t ZB_AGGU = 0;
constexpr size_t ZB_AGGD = (size_t)3 * NUD;
constexpr size_t ZB_SE   = ZB_AGGD + (size_t)3 * NID;
constexpr size_t ZB_DE   = ZB_SE + (size_t)3 * NUD;
constexpr size_t ZTOT    = ZB_DE + (size_t)3 * NID;

constexpr int SCAN_N   = 3 * NUc;                       // 300K user-side degrees
constexpr int NBLK_SCAN = (SCAN_N + 1023) / 1024;       // 293

// ---------------- device scratch (no allocation allowed) ----------------
__device__ float g_zbuf[ZTOT];
__device__ float g_seW[(size_t)3 * NUD];
__device__ float g_deW[(size_t)3 * NID];
__device__ float g_src[NUD];
__device__ float g_dst[NID];
__device__ float g_srcAll[NUD];
__device__ float g_dstAll[NID];
__device__ int   g_deg[3 * NUc + 3 * NIc];
__device__ float g_isqU[3 * NUc];
__device__ float g_isqV[3 * NIc];
__device__ float g_dU[3 * NUc];
__device__ float g_dV[3 * NIc];
// CSR (by user, all 3 types concatenated by global exclusive scan)
__device__ int g_csr[ETOT_E];
__device__ int g_tmpScan[SCAN_N];
__device__ int g_blkSum[512];
__device__ int g_blkSumScan[512];
__device__ int g_start[SCAN_N];
__device__ int g_cur[SCAN_N];

__device__ __forceinline__ float lrelu(float x) { return x >= 0.0f ? x : 0.01f * x; }

__device__ __forceinline__ void red4(float4* a, float x, float y, float z, float w) {
    asm volatile("red.global.add.v4.f32 [%0], {%1, %2, %3, %4};"
                 :: "l"(a), "f"(x), "f"(y), "f"(z), "f"(w) : "memory");
}

// ---------------- setup kernels ----------------

__global__ void zeroRange_k(size_t off4, size_t n4) {
    size_t i = (size_t)blockIdx.x * blockDim.x + threadIdx.x;
    if (i < n4) ((float4*)g_zbuf)[off4 + i] = make_float4(0.f, 0.f, 0.f, 0.f);
}

__global__ void zeroDeg_k() {
    int i = blockIdx.x * blockDim.x + threadIdx.x;
    if (i < 3 * (NUc + NIc)) g_deg[i] = 0;
}

__global__ void degCount_k(int t, const int* __restrict__ U, const int* __restrict__ V, int E) {
    int e = blockIdx.x * blockDim.x + threadIdx.x;
    if (e >= E) return;
    atomicAdd(&g_deg[t * NUc + U[e]], 1);
    atomicAdd(&g_deg[3 * NUc + t * NIc + V[e]], 1);
}

__global__ void degConv_k() {
    int i = blockIdx.x * blockDim.x + threadIdx.x;
    if (i < 3 * NUc) {
        float f = (float)max(g_deg[i], 1);
        g_dU[i] = f;
        g_isqU[i] = rsqrtf(f);
    } else if (i < 3 * (NUc + NIc)) {
        int j = i - 3 * NUc;
        float f = (float)max(g_deg[3 * NUc + j], 1);
        g_dV[j] = f;
        g_isqV[j] = rsqrtf(f);
    }
}

// ---- hierarchical exclusive scan of user-side degrees (3 types concatenated) ----
__global__ void blockScan_k() {
    __shared__ int wsum[32];
    int tid = threadIdx.x;
    int gi = blockIdx.x * 1024 + tid;
    int d = (gi < SCAN_N) ? g_deg[gi] : 0;
    int x = d;
#pragma unroll
    for (int o = 1; o < 32; o <<= 1) {
        int y = __shfl_up_sync(0xFFFFFFFFu, x, o);
        if ((tid & 31) >= o) x += y;
    }
    if ((tid & 31) == 31) wsum[tid >> 5] = x;
    __syncthreads();
    if (tid < 32) {
        int w = wsum[tid];
#pragma unroll
        for (int o = 1; o < 32; o <<= 1) {
            int y = __shfl_up_sync(0xFFFFFFFFu, w, o);
            if (tid >= o) w += y;
        }
        wsum[tid] = w;
    }
    __syncthreads();
    int incl = x + ((tid >= 32) ? wsum[(tid >> 5) - 1] : 0);
    if (gi < SCAN_N) g_tmpScan[gi] = incl - d;
    if (tid == 1023) g_blkSum[blockIdx.x] = incl;
}

__global__ void scanSums_k() {
    __shared__ int wsum[32];
    int tid = threadIdx.x;   // 512 threads, NBLK_SCAN <= 512
    int d = (tid < NBLK_SCAN) ? g_blkSum[tid] : 0;
    int x = d;
#pragma unroll
    for (int o = 1; o < 32; o <<= 1) {
        int y = __shfl_up_sync(0xFFFFFFFFu, x, o);
        if ((tid & 31) >= o) x += y;
    }
    if ((tid & 31) == 31) wsum[tid >> 5] = x;
    __syncthreads();
    if (tid < 32) {
        int w = (tid < 16) ? wsum[tid] : 0;
#pragma unroll
        for (int o = 1; o < 32; o <<= 1) {
            int y = __shfl_up_sync(0xFFFFFFFFu, w, o);
            if (tid >= o) w += y;
        }
        wsum[tid] = w;
    }
    __syncthreads();
    int incl = x + ((tid >= 32) ? wsum[(tid >> 5) - 1] : 0);
    if (tid < NBLK_SCAN) g_blkSumScan[tid] = incl;
}

__global__ void addOff_k() {
    int gi = blockIdx.x * 1024 + threadIdx.x;
    if (gi >= SCAN_N) return;
    int blk = gi >> 10;
    int s = g_tmpScan[gi] + (blk ? g_blkSumScan[blk - 1] : 0);
    g_start[gi] = s;
    g_cur[gi] = s;
}

__global__ void csrFill_k(int t, const int* __restrict__ U, int E) {
    int e = blockIdx.x * blockDim.x + threadIdx.x;
    if (e >= E) return;
    int u = U[e];
    int p = atomicAdd(&g_cur[t * NUc + u], 1);
    g_csr[p] = e;   // within-type edge index at global CSR position
}

__global__ void scaleInit_k(const float* __restrict__ emb, int items) {
    int i = blockIdx.x * blockDim.x + threadIdx.x;
    int n = items ? NID : NUD;
    if (i >= n) return;
    float v = emb[i] * A_SC;
    if (items) { g_dst[i] = v; g_dstAll[i] = v; }
    else       { g_src[i] = v; g_srcAll[i] = v; }
}

// ---------------- layer-0 edge pass: gather-by-u + scatter-to-v ----------------
// Per u (16 threads, float4 each): registers accumulate aggU (= sum dst[v]*sv*w)
// and se (= sum w); REDs scatter aggD (= src[u]*su*w) and de (= w).
__global__ void __launch_bounds__(256) gath0_k(const float* __restrict__ ew,
                                               int t, const int* __restrict__ V) {
    int gid = blockIdx.x * 256 + threadIdx.x;
    int u = gid >> 4, q = gid & 15;
    if (u >= NUc) return;
    int si = t * NUc + u;
    float su = g_isqU[si];
    float4 s = ((const float4*)g_src)[u * 16 + q];
    float4 ssu = make_float4(s.x * su, s.y * su, s.z * su, s.w * su);
    int beg = g_start[si];
    int end = (si + 1 < SCAN_N) ? g_start[si + 1] : ETOT_E;

    float4 accU = make_float4(0.f, 0.f, 0.f, 0.f);
    float4 accSe = make_float4(0.f, 0.f, 0.f, 0.f);
    float4* aggD = (float4*)(g_zbuf + ZB_AGGD + (size_t)t * NID);
    float4* de   = (float4*)(g_zbuf + ZB_DE   + (size_t)t * NID);

    int i = beg;
    int e_n = 0, v_n = 0;
    if (i < end) { e_n = __ldg(g_csr + i); v_n = __ldg(V + e_n); }
    while (i < end) {
        int e = e_n, v = v_n;
        i++;
        if (i < end) { e_n = __ldg(g_csr + i); v_n = __ldg(V + e_n); }
        float sv = g_isqV[t * NIc + v];
        float4 w = __ldcs((const float4*)ew + (size_t)e * 16 + q);
        w.x *= B_SC; w.y *= B_SC; w.z *= B_SC; w.w *= B_SC;
        float4 d = __ldg((const float4*)g_dst + v * 16 + q);
        accU.x = fmaf(d.x * sv, w.x, accU.x);
        accU.y = fmaf(d.y * sv, w.y, accU.y);
        accU.z = fmaf(d.z * sv, w.z, accU.z);
        accU.w = fmaf(d.w * sv, w.w, accU.w);
        accSe.x += w.x; accSe.y += w.y; accSe.z += w.z; accSe.w += w.w;
        red4(&aggD[v * 16 + q], ssu.x * w.x, ssu.y * w.y, ssu.z * w.z, ssu.w * w.w);
        red4(&de[v * 16 + q], w.x, w.y, w.z, w.w);
    }
    ((float4*)(g_zbuf + ZB_AGGU + (size_t)t * NUD))[u * 16 + q] = accU;
    ((float4*)(g_zbuf + ZB_SE   + (size_t)t * NUD))[u * 16 + q] = accSe;
}

// ---------------- layer-1 edge pass: edge weight computed inline ----------------
// w = lrelu((seW[u]+deW[v]) / (dU[u]+dV[v])); aggU register-accumulated,
// aggD scattered via RED. No se/de (dead after last layer), no edge array.
__global__ void __launch_bounds__(256) gath1_k(int t, const int* __restrict__ V) {
    int gid = blockIdx.x * 256 + threadIdx.x;
    int u = gid >> 4, q = gid & 15;
    if (u >= NUc) return;
    int si = t * NUc + u;
    float su = g_isqU[si];
    float du = g_dU[si];
    float4 s = ((const float4*)g_src)[u * 16 + q];
    float4 ssu = make_float4(s.x * su, s.y * su, s.z * su, s.w * su);
    float4 sw = ((const float4*)g_seW)[(size_t)t * NUc * 16 + u * 16 + q];
    int beg = g_start[si];
    int end = (si + 1 < SCAN_N) ? g_start[si + 1] : ETOT_E;

    float4 accU = make_float4(0.f, 0.f, 0.f, 0.f);
    float4* aggD = (float4*)(g_zbuf + ZB_AGGD + (size_t)t * NID);

    int i = beg;
    int e_n = 0, v_n = 0;
    if (i < end) { e_n = __ldg(g_csr + i); v_n = __ldg(V + e_n); }
    while (i < end) {
        int v = v_n;
        i++;
        if (i < end) { e_n = __ldg(g_csr + i); v_n = __ldg(V + e_n); }
        float sv = g_isqV[t * NIc + v];
        float dv = g_dV[t * NIc + v];
        float r = 1.0f / (du + dv);
        float4 dw = __ldg((const float4*)g_deW + (size_t)t * NIc * 16 + v * 16 + q);
        float4 w;
        w.x = lrelu((sw.x + dw.x) * r);
        w.y = lrelu((sw.y + dw.y) * r);
        w.z = lrelu((sw.z + dw.z) * r);
        w.w = lrelu((sw.w + dw.w) * r);
        float4 d = __ldg((const float4*)g_dst + v * 16 + q);
        accU.x = fmaf(d.x * sv, w.x, accU.x);
        accU.y = fmaf(d.y * sv, w.y, accU.y);
        accU.z = fmaf(d.z * sv, w.z, accU.z);
        accU.w = fmaf(d.w * sv, w.w, accU.w);
        red4(&aggD[v * 16 + q], ssu.x * w.x, ssu.y * w.y, ssu.z * w.z, ssu.w * w.w);
    }
    ((float4*)(g_zbuf + ZB_AGGU + (size_t)t * NUD))[u * 16 + q] = accU;
}

// ---------------- node kernels ----------------

__global__ void nodeCombine_k(const float* __restrict__ W, int items) {
    __shared__ float Ws[64 * 64];
    __shared__ float R[4][3][64];
    int tx = threadIdx.x, ty = threadIdx.y;
    int lin = ty * 64 + tx;
#pragma unroll
    for (int i = 0; i < 16; i++) Ws[lin + 256 * i] = W[lin + 256 * i];

    int N = items ? NIc : NUc;
    int nd = items ? NID : NUD;
    int n = blockIdx.x * 4 + ty;
    const float* agg = items ? (g_zbuf + ZB_AGGD) : (g_zbuf + ZB_AGGU);
    if (n < N) {
        R[ty][0][tx] = agg[(size_t)0 * nd + n * 64 + tx];
        R[ty][1][tx] = agg[(size_t)1 * nd + n * 64 + tx];
        R[ty][2][tx] = agg[(size_t)2 * nd + n * 64 + tx];
    }
    __syncthreads();
    if (n >= N) return;

    float s0 = 0.f, s1 = 0.f, s2 = 0.f;
#pragma unroll
    for (int k = 0; k < 64; k++) {
        float wk = Ws[k * 64 + tx];
        s0 = fmaf(R[ty][0][k], wk, s0);
        s1 = fmaf(R[ty][1][k], wk, s1);
        s2 = fmaf(R[ty][2][k], wk, s2);
    }
    const float* isq = items ? g_isqV : g_isqU;
    int NN = items ? NIc : NUc;
    float o = lrelu(s0 * isq[0 * NN + n]) + 0.5f * lrelu(s1 * isq[1 * NN + n])
            + 0.25f * lrelu(s2 * isq[2 * NN + n]);
    float* cur = items ? g_dst : g_src;
    float* acc = items ? g_dstAll : g_srcAll;
    cur[n * 64 + tx] = o;
    acc[n * 64 + tx] += o;
}

__global__ void seGemm_k(const float* __restrict__ W, int t, int items) {
    __shared__ float Ws[64 * 64];
    __shared__ float R[4][64];
    int tx = threadIdx.x, ty = threadIdx.y;
    int lin = ty * 64 + tx;
#pragma unroll
    for (int i = 0; i < 16; i++) Ws[lin + 256 * i] = W[lin + 256 * i];

    int N = items ? NIc : NUc;
    const float* in  = items ? (g_zbuf + ZB_DE + (size_t)t * NID)
                             : (g_zbuf + ZB_SE + (size_t)t * NUD);
    float* out = items ? (g_deW + (size_t)t * NID) : (g_seW + (size_t)t * NUD);
    int n = blockIdx.x * 4 + ty;
    if (n < N) R[ty][tx] = in[n * 64 + tx];
    __syncthreads();
    if (n >= N) return;

    float s = 0.f;
#pragma unroll
    for (int k = 0; k < 64; k++) s = fmaf(R[ty][k], Ws[k * 64 + tx], s);
    out[n * 64 + tx] = s;
}

__global__ void writeOut_k(float* __restrict__ out) {
    int i = blockIdx.x * blockDim.x + threadIdx.x;
    if (i < NUD) out[i] = g_srcAll[i] / 3.0f;
    else if (i < NUD + NID) out[i] = g_dstAll[i - NUD] / 3.0f;
}

// ---------------- launch ----------------
extern "C" void kernel_launch(void* const* d_in, const int* in_sizes, int n_in,
                              void* d_out, int out_size) {
    const float* user  = (const float*)d_in[0];
    const float* item  = (const float*)d_in[1];
    const float* ebuy  = (const float*)d_in[2];
    const float* ecart = (const float*)d_in[3];
    const float* epv   = (const float*)d_in[4];
    const float* nodeW = (const float*)d_in[5];
    const float* edgeW = (const float*)d_in[6];
    const int* bu = (const int*)d_in[7];
    const int* bv = (const int*)d_in[8];
    const int* cu = (const int*)d_in[9];
    const int* cv = (const int*)d_in[10];
    const int* pu = (const int*)d_in[11];
    const int* pvv = (const int*)d_in[12];
    float* out = (float*)d_out;

    const int TB = 256;
    auto nb = [](long long n, int tb) { return (unsigned)((n + tb - 1) / tb); };

    // degrees
    zeroDeg_k<<<nb(3 * (NUc + NIc), TB), TB>>>();
    degCount_k<<<nb(EBc, TB), TB>>>(0, bu, bv, EBc);
    degCount_k<<<nb(ECc, TB), TB>>>(1, cu, cv, ECc);
    degCount_k<<<nb(EPc, TB), TB>>>(2, pu, pvv, EPc);
    degConv_k<<<nb(3 * (NUc + NIc), TB), TB>>>();

    // CSR build (by user, all types via one global scan)
    blockScan_k<<<NBLK_SCAN, 1024>>>();
    scanSums_k<<<1, 512>>>();
    addOff_k<<<NBLK_SCAN, 1024>>>();
    csrFill_k<<<nb(EBc, TB), TB>>>(0, bu, EBc);
    csrFill_k<<<nb(ECc, TB), TB>>>(1, cu, ECc);
    csrFill_k<<<nb(EPc, TB), TB>>>(2, pu, EPc);

    scaleInit_k<<<nb(NUD, TB), TB>>>(user, 0);
    scaleInit_k<<<nb(NID, TB), TB>>>(item, 1);

    dim3 bt(64, 4);
    unsigned gGath = nb((long long)NUc * 16, 256);

    // -------- layer 0 --------
    // zero only RED targets: aggD + de (v-side)
    zeroRange_k<<<nb((long long)(3 * NID) / 4, TB), TB>>>(ZB_AGGD / 4, (size_t)3 * NID / 4);
    zeroRange_k<<<nb((long long)(3 * NID) / 4, TB), TB>>>(ZB_DE / 4, (size_t)3 * NID / 4);

    gath0_k<<<gGath, 256>>>(ebuy, 0, bv);
    gath0_k<<<gGath, 256>>>(ecart, 1, cv);
    gath0_k<<<gGath, 256>>>(epv, 2, pvv);

    nodeCombine_k<<<nb(NIc, 4), bt>>>(nodeW, 1);
    nodeCombine_k<<<nb(NUc, 4), bt>>>(nodeW, 0);

    for (int t = 0; t < 3; t++) {
        seGemm_k<<<nb(NUc, 4), bt>>>(edgeW, t, 0);
        seGemm_k<<<nb(NIc, 4), bt>>>(edgeW, t, 1);
    }

    // -------- layer 1 --------
    zeroRange_k<<<nb((long long)(3 * NID) / 4, TB), TB>>>(ZB_AGGD / 4, (size_t)3 * NID / 4);

    gath1_k<<<gGath, 256>>>(0, bv);
    gath1_k<<<gGath, 256>>>(1, cv);
    gath1_k<<<gGath, 256>>>(2, pvv);

    nodeCombine_k<<<nb(NIc, 4), bt>>>(nodeW + Dc * Dc, 1);
    nodeCombine_k<<<nb(NUc, 4), bt>>>(nodeW + Dc * Dc, 0);

    writeOut_k<<<nb(NUD + NID, TB), TB>>>(out);
}